// round 7
// baseline (speedup 1.0000x reference)
#include <cuda_runtime.h>
#include <cuda_fp16.h>
#include <cstdint>

#define BSZ   128
#define NNODE 4000
#define DF    128
#define NB    10
#define SEQ   400
#define C1    32
#define C2    32
#define MTILE 128
#define MTOT  (BSZ*SEQ)          // 51200
#define NCTA  (MTOT/MTILE)       // 400
#define NSTAGE 40                // NB * 4 quarter-K stages

// ---- shared memory byte layout --------------------------------------------
#define SMB_IDX   0                         // 1280 ints = 5120 B
#define SMB_A     5120                      // 4 x 16 KB fp32 quarter-K stages
#define A_STAGE   (MTILE*32*4)              // 16384
#define SMB_B     (SMB_A + 4*A_STAGE)       // 70656
#define B_STAGE   (16*160)                  // 2560 (16 pair-rows x 160B padded)
#define SMB_TOTAL (SMB_B + 4*B_STAGE)       // 80896  -> 2 CTAs/SM

__device__ uint32_t g_w1h[NB*64*40];  // f16 pairs: [k][pair(d/2)][c1], 40-u32 rows
__device__ float    g_partial[MTOT];
__device__ int      g_cnt[BSZ];       // zero-init; self-resetting per call

__device__ __forceinline__ uint32_t smem_u32(const void* p) {
    uint32_t a;
    asm("{ .reg .u64 t; cvta.to.shared.u64 t, %1; cvt.u32.u64 %0, t; }" : "=r"(a) : "l"(p));
    return a;
}
__device__ __forceinline__ void cp16(uint32_t dst, const void* src) {
    asm volatile("cp.async.cg.shared.global [%0], [%1], 16;" :: "r"(dst), "l"(src));
}
#define CP_COMMIT() asm volatile("cp.async.commit_group;" ::: "memory")
#define CP_WAIT(N)  asm volatile("cp.async.wait_group %0;" :: "n"(N) : "memory")

__device__ __forceinline__ uint32_t packh2(float2 v) {
    uint32_t r;
    asm("cvt.rn.f16x2.f32 %0, %1, %2;" : "=r"(r) : "f"(v.y), "f"(v.x));
    return r;
}
__device__ __forceinline__ void mma16816(float* c, uint32_t a0, uint32_t a1,
                                         uint32_t a2, uint32_t a3,
                                         uint32_t b0, uint32_t b1) {
    asm volatile(
        "mma.sync.aligned.m16n8k16.row.col.f32.f16.f16.f32 "
        "{%0,%1,%2,%3}, {%4,%5,%6,%7}, {%8,%9}, {%0,%1,%2,%3};"
        : "+f"(c[0]), "+f"(c[1]), "+f"(c[2]), "+f"(c[3])
        : "r"(a0), "r"(a1), "r"(a2), "r"(a3), "r"(b0), "r"(b1));
}

// ---------------------------------------------------------------------------
// prep: conv1 weights -> f16 pair-interleaved [k][d/2][c1] rows (40 u32 pad)
// ---------------------------------------------------------------------------
__global__ void prep_kernel(const float* __restrict__ w1) {
    int i = blockIdx.x * blockDim.x + threadIdx.x;     // 40960
    if (i >= NB * DF * C1) return;
    int k   = i >> 12;
    int rem = i & 4095;
    int d   = rem >> 5;
    int c1  = rem & 31;
    float v = w1[c1 * (DF * NB) + d * NB + k];
    ((__half*)g_w1h)[((size_t)k * 2560 + (d >> 1) * 40 + c1) * 2 + (d & 1)] =
        __float2half_rn(v);
}

// ---------------------------------------------------------------------------
// fused: deep cp.async pipeline + f16 mma conv1 + relu + conv2 + relu + FC
//        + deterministic last-CTA-per-graph final reduction
// ---------------------------------------------------------------------------
__global__ __launch_bounds__(256, 2) void conv_kernel(
    const int*   __restrict__ recep,
    const float* __restrict__ nf,
    const float* __restrict__ b1,
    const float* __restrict__ w2,
    const float* __restrict__ b2,
    const float* __restrict__ fcw,
    const float* __restrict__ fcb,
    float*       __restrict__ out)
{
    extern __shared__ char smem[];
    __shared__ int   sfin[2];
    __shared__ float sred[256];
    const uint32_t sbase = smem_u32(smem);
    int*   sIdx = (int*)(smem + SMB_IDX);
    const int tid  = threadIdx.x;
    const int wid  = tid >> 5;
    const int lane = tid & 31;
    const int m0   = blockIdx.x * MTILE;
    const int fr   = lane >> 2;      // 0..7
    const int fc   = lane & 3;       // 0..3

    for (int i = tid; i < MTILE * NB; i += 256) {
        int row = i / NB;
        int k   = i - row * NB;
        int m   = m0 + row;
        int b   = m / SEQ;
        int s   = m - b * SEQ;
        sIdx[i] = recep[b * NNODE + s * NB + k] + b * NNODE;
    }
    __syncthreads();

    // stage s: k = s>>2, quarter h = s&3 (32 K-cols), buffer bi = s&3
    auto prefetch = [&](int s) {
        const int k = s >> 2, h = s & 3, bi = s & 3;
        uint32_t abase = sbase + SMB_A + bi * A_STAGE;
#pragma unroll
        for (int j = 0; j < 4; j++) {
            int slot = tid + j * 256;              // 0..1023
            int row  = slot >> 3;
            int q    = slot & 7;
            int node = sIdx[row * NB + k];
            cp16(abase + (uint32_t)row * 128u + (uint32_t)((q ^ (row & 7)) * 16),
                 nf + (size_t)node * DF + h * 32 + q * 4);
        }
        if (tid < 160) {
            uint32_t bbase = sbase + SMB_B + bi * B_STAGE;
            const char* bsrc = (const char*)g_w1h + (size_t)k * 10240 + h * 2560;
            int row = tid / 10;
            int c   = tid - row * 10;
            cp16(bbase + (uint32_t)row * 160u + (uint32_t)c * 16u,
                 bsrc + row * 160 + c * 16);
        }
        CP_COMMIT();
    };

    prefetch(0); prefetch(1); prefetch(2);

    float acc[4][4];
#pragma unroll
    for (int nt = 0; nt < 4; nt++)
#pragma unroll
        for (int j = 0; j < 4; j++) acc[nt][j] = 0.f;

    const int row0 = wid * 16 + fr;
    const int oi   = (fc & 1) * 2;

    for (int s = 0; s < NSTAGE; s++) {
        const int bi = s & 3;
        if (s < NSTAGE - 2)      CP_WAIT(2);
        else if (s == NSTAGE - 2) CP_WAIT(1);
        else                      CP_WAIT(0);
        __syncthreads();   // stage s visible; all warps done reading stage s-1

        const float*    aw = (const float*)(smem + SMB_A + bi * A_STAGE);
        const uint32_t* bw = (const uint32_t*)(smem + SMB_B + bi * B_STAGE);
#pragma unroll
        for (int t = 0; t < 2; t++) {
            const int q0 = (4 * t + (fc >> 1)) ^ fr;       // cols 16t+2fc
            const int q1 = (4 * t + 2 + (fc >> 1)) ^ fr;   // cols 16t+8+2fc
            float2 v00 = *(const float2*)(aw + row0 * 32       + q0 * 4 + oi);
            float2 v10 = *(const float2*)(aw + (row0 + 8) * 32 + q0 * 4 + oi);
            float2 v01 = *(const float2*)(aw + row0 * 32       + q1 * 4 + oi);
            float2 v11 = *(const float2*)(aw + (row0 + 8) * 32 + q1 * 4 + oi);
            uint32_t a0 = packh2(v00), a1 = packh2(v10);
            uint32_t a2 = packh2(v01), a3 = packh2(v11);
            const int p0 = (8 * t + fc) * 40;
            const int p1 = (8 * t + 4 + fc) * 40;
#pragma unroll
            for (int nt = 0; nt < 4; nt++) {
                uint32_t b0 = bw[p0 + nt * 8 + fr];
                uint32_t b1v = bw[p1 + nt * 8 + fr];
                mma16816(acc[nt], a0, a1, a2, a3, b0, b1v);
            }
        }
        if (s + 3 < NSTAGE) prefetch(s + 3);   // writes buf (s-1)&3: readers done
    }
    __syncthreads();   // all bufs free

    // y1 = relu(conv1 + b1) -> smem [128][33]; w2 -> smem
    float* y1s = (float*)(smem + SMB_A);
    float* w2s = (float*)(smem + SMB_B);
    const int rb = wid * 16;
#pragma unroll
    for (int nt = 0; nt < 4; nt++) {
        int col = nt * 8 + 2 * fc;
        float bc0 = __ldg(b1 + col), bc1 = __ldg(b1 + col + 1);
        y1s[(rb + fr)     * 33 + col]     = fmaxf(acc[nt][0] + bc0, 0.f);
        y1s[(rb + fr)     * 33 + col + 1] = fmaxf(acc[nt][1] + bc1, 0.f);
        y1s[(rb + fr + 8) * 33 + col]     = fmaxf(acc[nt][2] + bc0, 0.f);
        y1s[(rb + fr + 8) * 33 + col + 1] = fmaxf(acc[nt][3] + bc1, 0.f);
    }
    ((float4*)w2s)[tid] = ((const float4*)w2)[tid & 255];
    __syncthreads();

    // conv2 (fp32) + relu + FC partial: one thread per row
    if (tid < MTILE) {
        int m = m0 + tid;
        int b = m / SEQ;
        int s = m - b * SEQ;
        const float* yr = y1s + tid * 33;
        float p = 0.f;
#pragma unroll
        for (int c2 = 0; c2 < C2; c2++) {
            float v = __ldg(b2 + c2);
            const float* wv = w2s + c2 * 32;
#pragma unroll
            for (int q = 0; q < 32; q += 4) {
                v = fmaf(wv[q],     yr[q],     v);
                v = fmaf(wv[q + 1], yr[q + 1], v);
                v = fmaf(wv[q + 2], yr[q + 2], v);
                v = fmaf(wv[q + 3], yr[q + 3], v);
            }
            v = fmaxf(v, 0.f);
            p = fmaf(v, __ldg(fcw + c2 * SEQ + s), p);
        }
        g_partial[m] = p;
        __threadfence();
    }
    __syncthreads();

    // --- deterministic final reduction: last CTA to finish a graph sums it
    if (tid == 0) {
        int bA = m0 / SEQ;
        int bB = (m0 + MTILE - 1) / SEQ;
        sfin[0] = -1; sfin[1] = -1;
#pragma unroll 2
        for (int j = 0; j < 2; j++) {
            int b = bA + j;
            if (b > bB) break;
            int lo = max(b * SEQ, m0);
            int hi = min((b + 1) * SEQ, m0 + MTILE);
            int my = hi - lo;
            int old = atomicAdd(&g_cnt[b], my);
            if (old + my == SEQ) sfin[j] = b;
        }
    }
    __syncthreads();

#pragma unroll 2
    for (int j = 0; j < 2; j++) {
        int b = sfin[j];
        if (b < 0) continue;
        __threadfence();                     // acquire partials of other CTAs
        float s = 0.f;
        for (int i = tid; i < SEQ; i += 256) s += g_partial[b * SEQ + i];
        sred[tid] = s;
        __syncthreads();
        for (int st = 128; st > 0; st >>= 1) {
            if (tid < st) sred[tid] += sred[tid + st];
            __syncthreads();
        }
        if (tid == 0) {
            out[b] = sred[0] + __ldg(fcb);
            g_cnt[b] = 0;                    // reset for next call / graph replay
        }
        __syncthreads();
    }
}

// ---------------------------------------------------------------------------
extern "C" void kernel_launch(void* const* d_in, const int* in_sizes, int n_in,
                              void* d_out, int out_size) {
    const int*   recep = (const int*)  d_in[0];
    const float* nf    = (const float*)d_in[1];
    const float* w1    = (const float*)d_in[2];
    const float* b1    = (const float*)d_in[3];
    const float* w2    = (const float*)d_in[4];
    const float* b2    = (const float*)d_in[5];
    const float* fcw   = (const float*)d_in[6];
    const float* fcb   = (const float*)d_in[7];
    float* out = (float*)d_out;

    cudaFuncSetAttribute(conv_kernel, cudaFuncAttributeMaxDynamicSharedMemorySize, SMB_TOTAL);
    prep_kernel<<<(NB*DF*C1 + 255) / 256, 256>>>(w1);
    conv_kernel<<<NCTA, 256, SMB_TOTAL>>>(recep, nf, b1, w2, b2, fcw, fcb, out);
}

// round 8
// speedup vs baseline: 1.1033x; 1.1033x over previous
#include <cuda_runtime.h>
#include <cuda_fp16.h>
#include <cstdint>

#define BSZ   128
#define NNODE 4000
#define DF    128
#define NB    10
#define SEQ   400
#define C1    32
#define C2    32
#define MTILE 128
#define MTOT  (BSZ*SEQ)          // 51200
#define NCTA  (MTOT/MTILE)       // 400
#define NSTAGE 20                // NB * 2 half-K stages

// ---- shared memory byte layout (dynamic) ----------------------------------
#define SMB_A     0                         // 2 x 32 KB fp32 half-K stages
#define A_STAGE   (MTILE*64*4)              // 32768
#define SMB_B     (2*A_STAGE)               // 65536
#define B_STAGE   (32*160)                  // 5120 (32 pair-rows x 160B padded)
#define SMB_TOTAL (SMB_B + 2*B_STAGE)       // 75776 -> 3 CTAs/SM

__device__ uint32_t g_w1h[NB*64*40];  // f16 pairs: [k][pair(d/2)][c1], 40-u32 rows
__device__ float    g_partial[MTOT];
__device__ int      g_cnt[BSZ];       // zero-init; self-resetting per call

__device__ __forceinline__ uint32_t smem_u32(const void* p) {
    uint32_t a;
    asm("{ .reg .u64 t; cvta.to.shared.u64 t, %1; cvt.u32.u64 %0, t; }" : "=r"(a) : "l"(p));
    return a;
}
__device__ __forceinline__ void cp16(uint32_t dst, const void* src) {
    asm volatile("cp.async.cg.shared.global [%0], [%1], 16;" :: "r"(dst), "l"(src));
}
#define CP_COMMIT() asm volatile("cp.async.commit_group;" ::: "memory")
#define CP_WAIT(N)  asm volatile("cp.async.wait_group %0;" :: "n"(N) : "memory")

__device__ __forceinline__ uint32_t packh2(float2 v) {
    uint32_t r;
    asm("cvt.rn.f16x2.f32 %0, %1, %2;" : "=r"(r) : "f"(v.y), "f"(v.x));
    return r;
}
__device__ __forceinline__ void mma16816(float* c, uint32_t a0, uint32_t a1,
                                         uint32_t a2, uint32_t a3,
                                         uint32_t b0, uint32_t b1) {
    asm volatile(
        "mma.sync.aligned.m16n8k16.row.col.f32.f16.f16.f32 "
        "{%0,%1,%2,%3}, {%4,%5,%6,%7}, {%8,%9}, {%0,%1,%2,%3};"
        : "+f"(c[0]), "+f"(c[1]), "+f"(c[2]), "+f"(c[3])
        : "r"(a0), "r"(a1), "r"(a2), "r"(a3), "r"(b0), "r"(b1));
}

// ---------------------------------------------------------------------------
// prep: conv1 weights -> f16 pair-interleaved [k][d/2][c1] rows (40 u32 pad)
// ---------------------------------------------------------------------------
__global__ void prep_kernel(const float* __restrict__ w1) {
    int i = blockIdx.x * blockDim.x + threadIdx.x;     // 40960
    if (i >= NB * DF * C1) return;
    int k   = i >> 12;
    int rem = i & 4095;
    int d   = rem >> 5;
    int c1  = rem & 31;
    float v = w1[c1 * (DF * NB) + d * NB + k];
    ((__half*)g_w1h)[((size_t)k * 2560 + (d >> 1) * 40 + c1) * 2 + (d & 1)] =
        __float2half_rn(v);
}

// ---------------------------------------------------------------------------
// fused: cp.async pipeline + f16 mma conv1 + relu + conv2 + relu + FC
//        + deterministic last-CTA-per-graph final reduction
// ---------------------------------------------------------------------------
__global__ __launch_bounds__(256, 3) void conv_kernel(
    const int*   __restrict__ recep,
    const float* __restrict__ nf,
    const float* __restrict__ b1,
    const float* __restrict__ w2,
    const float* __restrict__ b2,
    const float* __restrict__ fcw,
    const float* __restrict__ fcb,
    float*       __restrict__ out)
{
    extern __shared__ char smem[];
    __shared__ int   sfin[2];
    __shared__ float sred[256];
    const uint32_t sbase = smem_u32(smem);
    const int tid  = threadIdx.x;
    const int wid  = tid >> 5;
    const int lane = tid & 31;
    const int m0   = blockIdx.x * MTILE;
    const int fr   = lane >> 2;      // 0..7
    const int fc   = lane & 3;       // 0..3

    // stage s: k = s>>1, half h = s&1 (64 K-columns), buffer bi = s&1
    auto prefetch = [&](int s) {
        const int k = s >> 1, h = s & 1, bi = s & 1;
        uint32_t abase = sbase + SMB_A + bi * A_STAGE;
#pragma unroll
        for (int j = 0; j < 8; j++) {
            int slot = tid + j * 256;              // 0..2047
            int row  = slot >> 4;
            int q    = slot & 15;
            int m    = m0 + row;
            int b    = m / SEQ;
            int ss   = m - b * SEQ;
            int node = recep[b * NNODE + ss * NB + k] + b * NNODE;  // broadcast
            cp16(abase + (uint32_t)row * 256u +
                     (uint32_t)((q ^ ((row & 7) << 1)) * 16),
                 nf + (size_t)node * DF + h * 64 + q * 4);
        }
        uint32_t bbase = sbase + SMB_B + bi * B_STAGE;
        const char* bsrc = (const char*)g_w1h + (size_t)k * 10240 + h * 32 * 160;
#pragma unroll
        for (int j = 0; j < 2; j++) {
            int slot = tid + j * 256;              // 0..319
            if (slot < 320) {
                int row = slot / 10;
                int c   = slot - row * 10;
                cp16(bbase + (uint32_t)row * 160u + (uint32_t)c * 16u,
                     bsrc + row * 160 + c * 16);
            }
        }
        CP_COMMIT();
    };

    prefetch(0);
    prefetch(1);

    float acc[4][4];
#pragma unroll
    for (int nt = 0; nt < 4; nt++)
#pragma unroll
        for (int j = 0; j < 4; j++) acc[nt][j] = 0.f;

    const int row0 = wid * 16 + fr;
    const int sw   = fr << 1;
    const int oi   = (fc & 1) * 2;

    for (int s = 0; s < NSTAGE; s++) {
        const int bi = s & 1;
        if (s < NSTAGE - 1) CP_WAIT(1); else CP_WAIT(0);
        __syncthreads();

        const float*    aw = (const float*)(smem + SMB_A + bi * A_STAGE);
        const uint32_t* bw = (const uint32_t*)(smem + SMB_B + bi * B_STAGE);
#pragma unroll
        for (int t = 0; t < 4; t++) {
            const int q0 = (4 * t + (fc >> 1)) ^ sw;       // cols 16t+2fc
            const int q1 = (4 * t + 2 + (fc >> 1)) ^ sw;   // cols 16t+8+2fc
            float2 v00 = *(const float2*)(aw + row0 * 64       + q0 * 4 + oi);
            float2 v10 = *(const float2*)(aw + (row0 + 8) * 64 + q0 * 4 + oi);
            float2 v01 = *(const float2*)(aw + row0 * 64       + q1 * 4 + oi);
            float2 v11 = *(const float2*)(aw + (row0 + 8) * 64 + q1 * 4 + oi);
            uint32_t a0 = packh2(v00), a1 = packh2(v10);
            uint32_t a2 = packh2(v01), a3 = packh2(v11);
            const int p0 = (8 * t + fc) * 40;          // k = 16t+2fc,+1
            const int p1 = (8 * t + 4 + fc) * 40;      // k = 16t+8+2fc,+1
#pragma unroll
            for (int nt = 0; nt < 4; nt++) {
                uint32_t b0 = bw[p0 + nt * 8 + fr];
                uint32_t b1v = bw[p1 + nt * 8 + fr];
                mma16816(acc[nt], a0, a1, a2, a3, b0, b1v);
            }
        }
        __syncthreads();                            // done reading stage bi
        if (s + 2 < NSTAGE) prefetch(s + 2);        // refill freed buffer
    }

    // y1 = relu(conv1 + b1) -> smem [128][33]; w2 -> smem
    float* y1s = (float*)(smem + SMB_A);
    float* w2s = (float*)(smem + SMB_B);
    const int rb = wid * 16;
#pragma unroll
    for (int nt = 0; nt < 4; nt++) {
        int col = nt * 8 + 2 * fc;
        float bc0 = __ldg(b1 + col), bc1 = __ldg(b1 + col + 1);
        y1s[(rb + fr)     * 33 + col]     = fmaxf(acc[nt][0] + bc0, 0.f);
        y1s[(rb + fr)     * 33 + col + 1] = fmaxf(acc[nt][1] + bc1, 0.f);
        y1s[(rb + fr + 8) * 33 + col]     = fmaxf(acc[nt][2] + bc0, 0.f);
        y1s[(rb + fr + 8) * 33 + col + 1] = fmaxf(acc[nt][3] + bc1, 0.f);
    }
    ((float4*)w2s)[tid] = ((const float4*)w2)[tid & 255];
    __syncthreads();

    // conv2 (fp32) + relu + FC partial: one thread per row
    if (tid < MTILE) {
        int m = m0 + tid;
        int b = m / SEQ;
        int s = m - b * SEQ;
        const float* yr = y1s + tid * 33;
        float p = 0.f;
#pragma unroll
        for (int c2 = 0; c2 < C2; c2++) {
            float v = __ldg(b2 + c2);
            const float* wv = w2s + c2 * 32;
#pragma unroll
            for (int q = 0; q < 32; q += 4) {
                v = fmaf(wv[q],     yr[q],     v);
                v = fmaf(wv[q + 1], yr[q + 1], v);
                v = fmaf(wv[q + 2], yr[q + 2], v);
                v = fmaf(wv[q + 3], yr[q + 3], v);
            }
            v = fmaxf(v, 0.f);
            p = fmaf(v, __ldg(fcw + c2 * SEQ + s), p);
        }
        g_partial[m] = p;
        __threadfence();
    }
    __syncthreads();

    // --- deterministic final reduction: last CTA to finish a graph sums it
    if (tid == 0) {
        int bA = m0 / SEQ;
        int bB = (m0 + MTILE - 1) / SEQ;
        sfin[0] = -1; sfin[1] = -1;
#pragma unroll 2
        for (int j = 0; j < 2; j++) {
            int b = bA + j;
            if (b > bB) break;
            int lo = max(b * SEQ, m0);
            int hi = min((b + 1) * SEQ, m0 + MTILE);
            int my = hi - lo;
            int old = atomicAdd(&g_cnt[b], my);
            if (old + my == SEQ) sfin[j] = b;
        }
    }
    __syncthreads();

#pragma unroll 2
    for (int j = 0; j < 2; j++) {
        int b = sfin[j];
        if (b < 0) continue;
        __threadfence();                     // acquire other CTAs' partials
        float s = 0.f;
        for (int i = tid; i < SEQ; i += 256) s += g_partial[b * SEQ + i];
        sred[tid] = s;
        __syncthreads();
        for (int st = 128; st > 0; st >>= 1) {
            if (tid < st) sred[tid] += sred[tid + st];
            __syncthreads();
        }
        if (tid == 0) {
            out[b] = sred[0] + __ldg(fcb);
            g_cnt[b] = 0;                    // reset for graph replay
        }
        __syncthreads();
    }
}

// ---------------------------------------------------------------------------
extern "C" void kernel_launch(void* const* d_in, const int* in_sizes, int n_in,
                              void* d_out, int out_size) {
    const int*   recep = (const int*)  d_in[0];
    const float* nf    = (const float*)d_in[1];
    const float* w1    = (const float*)d_in[2];
    const float* b1    = (const float*)d_in[3];
    const float* w2    = (const float*)d_in[4];
    const float* b2    = (const float*)d_in[5];
    const float* fcw   = (const float*)d_in[6];
    const float* fcb   = (const float*)d_in[7];
    float* out = (float*)d_out;

    cudaFuncSetAttribute(conv_kernel, cudaFuncAttributeMaxDynamicSharedMemorySize, SMB_TOTAL);
    prep_kernel<<<(NB*DF*C1 + 255) / 256, 256>>>(w1);
    conv_kernel<<<NCTA, 256, SMB_TOTAL>>>(recep, nf, b1, w2, b2, fcw, fcb, out);
}